// round 5
// baseline (speedup 1.0000x reference)
#include <cuda_runtime.h>
#include <cuda_bf16.h>
#include <math.h>
#include <stdint.h>

#define BATCH 128
#define NOSC  1024
#define STEPS 10
#define DT    0.1f
#define BN    (BATCH*NOSC)

#define TM 32                 // batch rows per CTA
#define TN 32                 // osc cols per CTA
#define KS 64                 // k elements per pipeline stage
#define NSTAGE (NOSC/KS)      // 16
#define NCTA 128
#define LDA 72                // smem row stride (bf16): 144B, ldmatrix conflict-free
#define TILE_E (32*LDA)
#define STG_E  (3*TILE_E)
#define SMEM_BYTES (4*STG_E*2)  // 4-stage ring = 55296 B

// ---------------- persistent device state (no allocation allowed) -------------
__device__ float          g_theta[BN];
__device__ __nv_bfloat16  g_sinb[2][BN];
__device__ __nv_bfloat16  g_cosb[2][BN];
__device__ __nv_bfloat16  g_Kb[NOSC*NOSC];
__device__ unsigned       g_bar_count;
__device__ volatile int   g_sense;

// ---------------- helpers -----------------------------------------------------
__device__ __forceinline__ uint32_t s2u(const void* p) {
    return (uint32_t)__cvta_generic_to_shared(p);
}
__device__ __forceinline__ void cp16cg(void* dst, const void* src) {  // L1-bypass
    asm volatile("cp.async.cg.shared.global [%0], [%1], 16;"
                 :: "r"(s2u(dst)), "l"(src) : "memory");
}
__device__ __forceinline__ void cp16ca(void* dst, const void* src) {  // L1-cached
    asm volatile("cp.async.ca.shared.global [%0], [%1], 16;"
                 :: "r"(s2u(dst)), "l"(src) : "memory");
}
__device__ __forceinline__ void ldsm4(uint32_t& r0, uint32_t& r1, uint32_t& r2,
                                      uint32_t& r3, const void* p) {
    asm volatile("ldmatrix.sync.aligned.m8n8.x4.shared.b16 {%0,%1,%2,%3}, [%4];"
                 : "=r"(r0), "=r"(r1), "=r"(r2), "=r"(r3) : "r"(s2u(p)));
}
__device__ __forceinline__ void ldsm2(uint32_t& r0, uint32_t& r1, const void* p) {
    asm volatile("ldmatrix.sync.aligned.m8n8.x2.shared.b16 {%0,%1}, [%2];"
                 : "=r"(r0), "=r"(r1) : "r"(s2u(p)));
}
__device__ __forceinline__ void mma16816(float* d, const uint32_t* a,
                                         uint32_t b0, uint32_t b1) {
    asm volatile(
        "mma.sync.aligned.m16n8k16.row.col.f32.bf16.bf16.f32 "
        "{%0,%1,%2,%3}, {%4,%5,%6,%7}, {%8,%9}, {%0,%1,%2,%3};"
        : "+f"(d[0]), "+f"(d[1]), "+f"(d[2]), "+f"(d[3])
        : "r"(a[0]), "r"(a[1]), "r"(a[2]), "r"(a[3]), "r"(b0), "r"(b1));
}

// ---------------- init: theta/sin/cos(buf 0) + K -> bf16 + barrier reset ------
__global__ void init_kernel(const float* __restrict__ theta_init,
                            const float* __restrict__ K) {
    int idx = blockIdx.x * blockDim.x + threadIdx.x;
    if (idx == 0) { g_bar_count = 0; g_sense = 0; }
    g_Kb[idx] = __float2bfloat16(K[idx]);
    if (idx < BN) {
        float t = theta_init[idx];
        g_theta[idx]   = t;
        g_sinb[0][idx] = __float2bfloat16(sinf(t));
        g_cosb[0][idx] = __float2bfloat16(cosf(t));
    }
}

// ---------------- persistent simulation kernel --------------------------------
__global__ __launch_bounds__(256, 1) void sim_kernel(const float* __restrict__ omega,
                                                     const float* __restrict__ kg) {
    extern __shared__ __nv_bfloat16 sm[];

    const int tid  = threadIdx.x;
    const int lane = tid & 31;
    const int wid  = tid >> 5;
    const int n0   = blockIdx.x * TN;     // 32 n-tiles
    const int m0   = blockIdx.y * TM;     // 4 m-tiles
    const int wy   = wid & 1;
    const int wn   = wid >> 1;

    const int lr = tid >> 3;
    const int lc = (tid & 7) * 8;

    const int ar  = wy * 16 + ((lane >> 3) & 1) * 8 + (lane & 7);
    const int l15 = lane & 15;
    const int br  = wn * 8 + (l15 & 7);
    const int bkh = ((l15 >> 3) & 1) * 8;

    // ---- owned epilogue coords: m = m0+wy*16+half*8+g, osc = oscb + cc -------
    const int g   = lane >> 2, tig = lane & 3;
    const int oscb = n0 + wn * 8 + tig * 2;
    const float scale = kg[0] * (1.0f / NOSC);
    const float om0 = omega[oscb], om1 = omega[oscb + 1];

    float th[2][2], so[2][2], co[2][2];
#pragma unroll
    for (int half = 0; half < 2; half++) {
        int m = m0 + wy * 16 + half * 8 + g;
#pragma unroll
        for (int cc = 0; cc < 2; cc++) {
            float t = g_theta[m * NOSC + oscb + cc];
            th[half][cc] = t;
            so[half][cc] = sinf(t);
            co[half][cc] = cosf(t);
        }
    }

#pragma unroll 1
    for (int s = 0; s < STEPS; s++) {
        const __nv_bfloat16* sin_r = g_sinb[s & 1];
        const __nv_bfloat16* cos_r = g_cosb[s & 1];
        const int wb = (s & 1) ^ 1;

        auto load_stage = [&](int st_i) {
            __nv_bfloat16* st = sm + (st_i & 3) * STG_E;
            const int k0 = st_i * KS;
            cp16cg(st + lr * LDA + lc,              sin_r + (size_t)(m0 + lr) * NOSC + k0 + lc);
            cp16cg(st + TILE_E + lr * LDA + lc,     cos_r + (size_t)(m0 + lr) * NOSC + k0 + lc);
            cp16ca(st + 2 * TILE_E + lr * LDA + lc, g_Kb  + (size_t)(n0 + lr) * NOSC + k0 + lc);
            asm volatile("cp.async.commit_group;" ::: "memory");
        };

        float aS[4] = {}, aC[4] = {};
        load_stage(0);
        load_stage(1);

#pragma unroll 1
        for (int st_i = 0; st_i < NSTAGE; st_i++) {
            if (st_i + 2 < NSTAGE) {
                load_stage(st_i + 2);
                asm volatile("cp.async.wait_group 2;" ::: "memory");
            } else if (st_i + 1 < NSTAGE) {
                asm volatile("cp.async.wait_group 1;" ::: "memory");
            } else {
                asm volatile("cp.async.wait_group 0;" ::: "memory");
            }
            __syncthreads();

            const __nv_bfloat16* st = sm + (st_i & 3) * STG_E;
#pragma unroll
            for (int kk = 0; kk < 4; kk++) {
                const int k0 = kk * 16;
                const int ac = k0 + (lane >> 4) * 8;
                uint32_t sa[4], ca[4], b0, b1;
                ldsm4(sa[0], sa[1], sa[2], sa[3], st + ar * LDA + ac);
                ldsm4(ca[0], ca[1], ca[2], ca[3], st + TILE_E + ar * LDA + ac);
                ldsm2(b0, b1, st + 2 * TILE_E + br * LDA + k0 + bkh);
                mma16816(aS, sa, b0, b1);
                mma16816(aC, ca, b0, b1);
            }
        }
        __syncthreads();   // all smem reads done before next step's loads reuse ring

        // ---- epilogue: register-resident phase update, bf16 publish ----------
#pragma unroll
        for (int half = 0; half < 2; half++) {
            int m = m0 + wy * 16 + half * 8 + g;
            __nv_bfloat162 sp, cp2;
#pragma unroll
            for (int cc = 0; cc < 2; cc++) {
                float S = aS[half * 2 + cc], C = aC[half * 2 + cc];
                float om = cc ? om1 : om0;
                float t2 = th[half][cc]
                         + DT * (om + scale * (co[half][cc] * S - so[half][cc] * C));
                float sn, cn;
                __sincosf(t2, &sn, &cn);
                th[half][cc] = t2;          // unwrapped; wrap is 2*pi-invariant
                so[half][cc] = sn;
                co[half][cc] = cn;
            }
            sp  = __floats2bfloat162_rn(so[half][0], so[half][1]);
            cp2 = __floats2bfloat162_rn(co[half][0], co[half][1]);
            *(__nv_bfloat162*)&g_sinb[wb][m * NOSC + oscb] = sp;
            *(__nv_bfloat162*)&g_cosb[wb][m * NOSC + oscb] = cp2;
        }

        // ---- grid barrier (sense = s+1), publishes sin/cos to all CTAs -------
        __syncthreads();
        if (tid == 0) {
            __threadfence();
            if (atomicAdd(&g_bar_count, 1u) == NCTA - 1u) {
                g_bar_count = 0;
                __threadfence();
                g_sense = s + 1;
            } else {
                while (g_sense < s + 1) { }
            }
        }
        __syncthreads();
    }

    // ---- write final theta (only consumer is finalize_kernel) ----------------
#pragma unroll
    for (int half = 0; half < 2; half++) {
        int m = m0 + wy * 16 + half * 8 + g;
#pragma unroll
        for (int cc = 0; cc < 2; cc++)
            g_theta[m * NOSC + oscb + cc] = th[half][cc];
    }
}

// ---------------- finalize: wrap + coherence (accurate fp32) ------------------
__global__ void finalize_kernel(float* __restrict__ out) {
    __shared__ float rs[256], rc[256];
    const int b = blockIdx.x, tid = threadIdx.x;
    float ss = 0.f, cs = 0.f;
    for (int j = tid; j < NOSC; j += 256) {
        int idx = b * NOSC + j;
        float t = g_theta[idx];
        float sn = sinf(t), cn = cosf(t);
        out[idx] = atan2f(sn, cn);        // wrap to (-pi, pi], matches reference
        ss += sn; cs += cn;
    }
    rs[tid] = ss; rc[tid] = cs;
    __syncthreads();
    for (int off = 128; off > 0; off >>= 1) {
        if (tid < off) { rs[tid] += rs[tid + off]; rc[tid] += rc[tid + off]; }
        __syncthreads();
    }
    if (tid == 0) {
        float sm2 = rs[0] * (1.0f / NOSC);
        float cm  = rc[0] * (1.0f / NOSC);
        out[BN + b] = sqrtf(cm * cm + sm2 * sm2);
    }
}

extern "C" void kernel_launch(void* const* d_in, const int* in_sizes, int n_in,
                              void* d_out, int out_size) {
    const float* theta_init = (const float*)d_in[0];
    const float* K          = (const float*)d_in[1];
    const float* omega      = (const float*)d_in[2];
    const float* kglobal    = (const float*)d_in[3];
    float* out = (float*)d_out;

    cudaFuncSetAttribute(sim_kernel, cudaFuncAttributeMaxDynamicSharedMemorySize,
                         SMEM_BYTES);

    init_kernel<<<(NOSC * NOSC) / 256, 256>>>(theta_init, K);
    dim3 grid(NOSC / TN, BATCH / TM);     // (32, 4) = 128 CTAs, all co-resident
    sim_kernel<<<grid, 256, SMEM_BYTES>>>(omega, kglobal);
    finalize_kernel<<<BATCH, 256>>>(out);
}